// round 2
// baseline (speedup 1.0000x reference)
#include <cuda_runtime.h>
#include <stdint.h>

// Problem constants (shapes are fixed by the dataset)
#define F_IN 128
#define HID  16
#define NCLS 8
#define MAX_N 100000

// Scratch (allocation-free rule: __device__ globals)
__device__ float g_deg [MAX_N];
__device__ float g_dinv[MAX_N];
__device__ float g_h1  [MAX_N * HID];   // x @ W1
__device__ float g_agg1[MAX_N * HID];   // aggregated layer-1 (incl. self loop)
__device__ float g_h2  [MAX_N * NCLS];  // relu(agg1+b1) @ W2
__device__ float g_agg2[MAX_N * NCLS];  // aggregated layer-2 (incl. self loop)

// ---------------------------------------------------------------------------
// 1) deg init: self-loop contributes 1 to every node's degree
__global__ void k_init_deg(int n) {
    int i = blockIdx.x * blockDim.x + threadIdx.x;
    if (i < n) g_deg[i] = 1.0f;
}

// 2) h1 = x @ W1   (thread = one (node, hid) pair; W1 staged in shared)
__global__ void k_xw1(const float* __restrict__ x, const float* __restrict__ W1, int n) {
    __shared__ float sW1[F_IN * HID]; // 8 KB
    for (int i = threadIdx.x; i < F_IN * HID; i += blockDim.x)
        sW1[i] = W1[i];
    __syncthreads();

    int gid = blockIdx.x * blockDim.x + threadIdx.x;
    int node = gid / HID;
    int j    = gid % HID;
    if (node >= n) return;

    const float* xr = x + (size_t)node * F_IN;
    float acc = 0.0f;
    #pragma unroll 16
    for (int k = 0; k < F_IN; k++)
        acc = fmaf(__ldg(xr + k), sW1[k * HID + j], acc);
    g_h1[node * HID + j] = acc;
}

// 3) degree scatter over edges (dst side)  [edge_index is int32: JAX x64 disabled]
__global__ void k_deg_scatter(const int* __restrict__ dst, int e) {
    int i = blockIdx.x * blockDim.x + threadIdx.x;
    if (i < e) atomicAdd(&g_deg[dst[i]], 1.0f);
}

// 4) dinv = rsqrt(deg); fuse self-loop init of agg1: agg1[n] = dinv^2 * h1[n]
__global__ void k_dinv_self1(int n) {
    int i = blockIdx.x * blockDim.x + threadIdx.x;
    if (i >= n) return;
    float di = rsqrtf(g_deg[i]);   // deg >= 1 always (self loop)
    g_dinv[i] = di;
    float w = di * di;
    #pragma unroll
    for (int j = 0; j < HID; j++)
        g_agg1[i * HID + j] = w * g_h1[i * HID + j];
}

// 5) layer-1 edge scatter: 16 consecutive threads per edge (one per feature)
__global__ void k_edge1(const int* __restrict__ src,
                        const int* __restrict__ dst, int e) {
    long long gid = (long long)blockIdx.x * blockDim.x + threadIdx.x;
    long long eidx = gid >> 4;          // /16
    int j = (int)(gid & 15);
    if (eidx >= e) return;
    int s = src[eidx];
    int d = dst[eidx];
    float w = g_dinv[s] * g_dinv[d];
    atomicAdd(&g_agg1[d * HID + j], w * g_h1[s * HID + j]);
}

// 6) h2 = relu(agg1 + b1) @ W2; fuse self-loop init of agg2
__global__ void k_layer2_self2(const float* __restrict__ b1,
                               const float* __restrict__ W2, int n) {
    __shared__ float sW2[HID * NCLS]; // 128 floats
    __shared__ float sb1[HID];
    if (threadIdx.x < HID * NCLS) sW2[threadIdx.x] = W2[threadIdx.x];
    if (threadIdx.x < HID) sb1[threadIdx.x] = b1[threadIdx.x];
    __syncthreads();

    int gid = blockIdx.x * blockDim.x + threadIdx.x;
    int node = gid / NCLS;
    int c    = gid % NCLS;
    if (node >= n) return;

    float acc = 0.0f;
    #pragma unroll
    for (int j = 0; j < HID; j++) {
        float v = g_agg1[node * HID + j] + sb1[j];
        v = fmaxf(v, 0.0f);
        acc = fmaf(v, sW2[j * NCLS + c], acc);
    }
    g_h2[node * NCLS + c] = acc;
    float di = g_dinv[node];
    g_agg2[node * NCLS + c] = di * di * acc;
}

// 7) layer-2 edge scatter: 8 consecutive threads per edge
__global__ void k_edge2(const int* __restrict__ src,
                        const int* __restrict__ dst, int e) {
    long long gid = (long long)blockIdx.x * blockDim.x + threadIdx.x;
    long long eidx = gid >> 3;          // /8
    int c = (int)(gid & 7);
    if (eidx >= e) return;
    int s = src[eidx];
    int d = dst[eidx];
    float w = g_dinv[s] * g_dinv[d];
    atomicAdd(&g_agg2[d * NCLS + c], w * g_h2[s * NCLS + c]);
}

// 8) logits = agg2 + b2 -> log_softmax per row (thread per node)
__global__ void k_logsoftmax(const float* __restrict__ b2,
                             float* __restrict__ out, int n) {
    __shared__ float sb2[NCLS];
    if (threadIdx.x < NCLS) sb2[threadIdx.x] = b2[threadIdx.x];
    __syncthreads();

    int i = blockIdx.x * blockDim.x + threadIdx.x;
    if (i >= n) return;

    float z[NCLS];
    float m = -1e30f;
    #pragma unroll
    for (int c = 0; c < NCLS; c++) {
        z[c] = g_agg2[i * NCLS + c] + sb2[c];
        m = fmaxf(m, z[c]);
    }
    float sum = 0.0f;
    #pragma unroll
    for (int c = 0; c < NCLS; c++)
        sum += expf(z[c] - m);
    float lse = m + logf(sum);
    #pragma unroll
    for (int c = 0; c < NCLS; c++)
        out[i * NCLS + c] = z[c] - lse;
}

// ---------------------------------------------------------------------------
extern "C" void kernel_launch(void* const* d_in, const int* in_sizes, int n_in,
                              void* d_out, int out_size) {
    const float* x  = (const float*)d_in[0];
    const int*   ei = (const int*)d_in[1];    // [2, E] int32 (JAX x64 disabled)
    const float* W1 = (const float*)d_in[2];
    const float* b1 = (const float*)d_in[3];
    const float* W2 = (const float*)d_in[4];
    const float* b2 = (const float*)d_in[5];
    float*       out = (float*)d_out;

    const int n = in_sizes[0] / F_IN;      // 100000
    const int e = in_sizes[1] / 2;         // 3200000
    const int* src = ei;                   // edge_index[0]
    const int* dst = ei + e;               // edge_index[1]

    const int T = 256;

    k_init_deg<<<(n + T - 1) / T, T>>>(n);
    k_xw1<<<((long long)n * HID + T - 1) / T, T>>>(x, W1, n);
    k_deg_scatter<<<(e + T - 1) / T, T>>>(dst, e);
    k_dinv_self1<<<(n + T - 1) / T, T>>>(n);
    {
        long long total = (long long)e * HID;
        k_edge1<<<(unsigned)((total + T - 1) / T), T>>>(src, dst, e);
    }
    k_layer2_self2<<<((long long)n * NCLS + T - 1) / T, T>>>(b1, W2, n);
    {
        long long total = (long long)e * NCLS;
        k_edge2<<<(unsigned)((total + T - 1) / T), T>>>(src, dst, e);
    }
    k_logsoftmax<<<(n + T - 1) / T, T>>>(b2, out, n);
}

// round 3
// speedup vs baseline: 1.4274x; 1.4274x over previous
#include <cuda_runtime.h>
#include <stdint.h>

#define F_IN 128
#define HID  16
#define NCLS 8
#define MAX_N 100000

__device__ float g_deg [MAX_N];
__device__ float g_dinv[MAX_N];
__device__ float g_h1  [MAX_N * HID];
__device__ float g_agg1[MAX_N * HID];
__device__ float g_h2  [MAX_N * NCLS];
__device__ float g_agg2[MAX_N * NCLS];

__device__ __forceinline__ void red_add_v4(float* p, float4 v) {
    asm volatile("red.global.add.v4.f32 [%0], {%1, %2, %3, %4};"
                 :: "l"(p), "f"(v.x), "f"(v.y), "f"(v.z), "f"(v.w) : "memory");
}

// 1) deg init: self-loop contributes 1
__global__ void k_init_deg(int n) {
    int i = blockIdx.x * blockDim.x + threadIdx.x;
    if (i < n) g_deg[i] = 1.0f;
}

// 2) h1 = x @ W1 (16 threads per node, one per hid; W1 in shared)
__global__ void k_xw1(const float* __restrict__ x, const float* __restrict__ W1, int n) {
    __shared__ float sW1[F_IN * HID];
    for (int i = threadIdx.x; i < F_IN * HID; i += blockDim.x)
        sW1[i] = W1[i];
    __syncthreads();

    int gid = blockIdx.x * blockDim.x + threadIdx.x;
    int node = gid / HID;
    int j    = gid % HID;
    if (node >= n) return;

    const float* xr = x + (size_t)node * F_IN;
    float acc = 0.0f;
    #pragma unroll 16
    for (int k = 0; k < F_IN; k++)
        acc = fmaf(__ldg(xr + k), sW1[k * HID + j], acc);
    g_h1[node * HID + j] = acc;
}

// 3) degree scatter (dst side)
__global__ void k_deg_scatter(const int* __restrict__ dst, int e) {
    int i = blockIdx.x * blockDim.x + threadIdx.x;
    if (i < e) atomicAdd(&g_deg[dst[i]], 1.0f);
}

// 4) dinv + self-loop init of agg1, float4-coalesced (4 threads per node)
__global__ void k_dinv_self1(int n) {
    int tid = blockIdx.x * blockDim.x + threadIdx.x;
    int node = tid >> 2;
    int j    = tid & 3;
    if (node >= n) return;
    float di = rsqrtf(g_deg[node]);     // broadcast load (same addr in 4 lanes)
    if (j == 0) g_dinv[node] = di;
    float w = di * di;
    float4 h = *(const float4*)(g_h1 + node * HID + j * 4);
    float4 o = make_float4(w * h.x, w * h.y, w * h.z, w * h.w);
    *(float4*)(g_agg1 + node * HID + j * 4) = o;
}

// 5) layer-1 edge scatter: 4 threads per edge, float4 gather + v4 RED
__global__ void k_edge1(const int* __restrict__ src,
                        const int* __restrict__ dst, int e) {
    long long gid = (long long)blockIdx.x * blockDim.x + threadIdx.x;
    int eidx = (int)(gid >> 2);
    int j = (int)(gid & 3);
    if (eidx >= e) return;
    int s = src[eidx];
    int d = dst[eidx];
    float w = g_dinv[s] * g_dinv[d];
    float4 h = *(const float4*)(g_h1 + s * HID + j * 4);
    float4 m = make_float4(w * h.x, w * h.y, w * h.z, w * h.w);
    red_add_v4(g_agg1 + d * HID + j * 4, m);
}

// 6) h2 = relu(agg1 + b1) @ W2; fused self-loop init of agg2
__global__ void k_layer2_self2(const float* __restrict__ b1,
                               const float* __restrict__ W2, int n) {
    __shared__ float sW2[HID * NCLS];
    __shared__ float sb1[HID];
    if (threadIdx.x < HID * NCLS) sW2[threadIdx.x] = W2[threadIdx.x];
    if (threadIdx.x < HID) sb1[threadIdx.x] = b1[threadIdx.x];
    __syncthreads();

    int gid = blockIdx.x * blockDim.x + threadIdx.x;
    int node = gid / NCLS;
    int c    = gid % NCLS;
    if (node >= n) return;

    float acc = 0.0f;
    #pragma unroll
    for (int j = 0; j < HID; j++) {
        float v = g_agg1[node * HID + j] + sb1[j];
        v = fmaxf(v, 0.0f);
        acc = fmaf(v, sW2[j * NCLS + c], acc);
    }
    g_h2[node * NCLS + c] = acc;
    float di = g_dinv[node];
    g_agg2[node * NCLS + c] = di * di * acc;
}

// 7) layer-2 edge scatter: 2 threads per edge, float4 gather + v4 RED
__global__ void k_edge2(const int* __restrict__ src,
                        const int* __restrict__ dst, int e) {
    long long gid = (long long)blockIdx.x * blockDim.x + threadIdx.x;
    int eidx = (int)(gid >> 1);
    int j = (int)(gid & 1);
    if (eidx >= e) return;
    int s = src[eidx];
    int d = dst[eidx];
    float w = g_dinv[s] * g_dinv[d];
    float4 h = *(const float4*)(g_h2 + s * NCLS + j * 4);
    float4 m = make_float4(w * h.x, w * h.y, w * h.z, w * h.w);
    red_add_v4(g_agg2 + d * NCLS + j * 4, m);
}

// 8) log_softmax per node (float4 loads)
__global__ void k_logsoftmax(const float* __restrict__ b2,
                             float* __restrict__ out, int n) {
    __shared__ float sb2[NCLS];
    if (threadIdx.x < NCLS) sb2[threadIdx.x] = b2[threadIdx.x];
    __syncthreads();

    int i = blockIdx.x * blockDim.x + threadIdx.x;
    if (i >= n) return;

    float4 a = *(const float4*)(g_agg2 + i * NCLS);
    float4 b = *(const float4*)(g_agg2 + i * NCLS + 4);
    float z[NCLS] = {a.x + sb2[0], a.y + sb2[1], a.z + sb2[2], a.w + sb2[3],
                     b.x + sb2[4], b.y + sb2[5], b.z + sb2[6], b.w + sb2[7]};
    float m = z[0];
    #pragma unroll
    for (int c = 1; c < NCLS; c++) m = fmaxf(m, z[c]);
    float sum = 0.0f;
    #pragma unroll
    for (int c = 0; c < NCLS; c++) sum += expf(z[c] - m);
    float lse = m + logf(sum);
    float4 o0 = make_float4(z[0]-lse, z[1]-lse, z[2]-lse, z[3]-lse);
    float4 o1 = make_float4(z[4]-lse, z[5]-lse, z[6]-lse, z[7]-lse);
    *(float4*)(out + i * NCLS)     = o0;
    *(float4*)(out + i * NCLS + 4) = o1;
}

// ---------------------------------------------------------------------------
extern "C" void kernel_launch(void* const* d_in, const int* in_sizes, int n_in,
                              void* d_out, int out_size) {
    const float* x  = (const float*)d_in[0];
    const int*   ei = (const int*)d_in[1];    // [2, E] int32
    const float* W1 = (const float*)d_in[2];
    const float* b1 = (const float*)d_in[3];
    const float* W2 = (const float*)d_in[4];
    const float* b2 = (const float*)d_in[5];
    float*       out = (float*)d_out;

    const int n = in_sizes[0] / F_IN;      // 100000
    const int e = in_sizes[1] / 2;         // 3200000
    const int* src = ei;
    const int* dst = ei + e;

    const int T = 256;

    k_init_deg<<<(n + T - 1) / T, T>>>(n);
    k_xw1<<<((long long)n * HID + T - 1) / T, T>>>(x, W1, n);
    k_deg_scatter<<<(e + T - 1) / T, T>>>(dst, e);
    k_dinv_self1<<<((long long)n * 4 + T - 1) / T, T>>>(n);
    {
        long long total = (long long)e * 4;
        k_edge1<<<(unsigned)((total + T - 1) / T), T>>>(src, dst, e);
    }
    k_layer2_self2<<<((long long)n * NCLS + T - 1) / T, T>>>(b1, W2, n);
    {
        long long total = (long long)e * 2;
        k_edge2<<<(unsigned)((total + T - 1) / T), T>>>(src, dst, e);
    }
    k_logsoftmax<<<(n + T - 1) / T, T>>>(b2, out, n);
}

// round 5
// speedup vs baseline: 1.4779x; 1.0354x over previous
#include <cuda_runtime.h>
#include <stdint.h>

#define F_IN 128
#define HID  16
#define NCLS 8
#define MAX_N 100000
#define MAX_E 3200000

__device__ float g_deg [MAX_N];
__device__ float g_dinv[MAX_N];
__device__ float g_w   [MAX_E];         // per-edge norm weight
__device__ float g_h1  [MAX_N * HID];
__device__ float g_agg1[MAX_N * HID];
__device__ float g_h2  [MAX_N * NCLS];
__device__ float g_agg2[MAX_N * NCLS];

__device__ __forceinline__ void red_add_v4(float* p, float4 v) {
    asm volatile("red.global.add.v4.f32 [%0], {%1, %2, %3, %4};"
                 :: "l"(p), "f"(v.x), "f"(v.y), "f"(v.z), "f"(v.w) : "memory");
}

// 1) deg init: self-loop contributes 1
__global__ void k_init_deg(int n) {
    int i = blockIdx.x * blockDim.x + threadIdx.x;
    if (i < n) g_deg[i] = 1.0f;
}

// 2) h1 = x @ W1 (16 threads/node; W1 in shared; x row broadcast within group)
__global__ void k_xw1(const float* __restrict__ x, const float* __restrict__ W1, int n) {
    __shared__ float sW1[F_IN * HID];
    for (int i = threadIdx.x; i < F_IN * HID; i += blockDim.x)
        sW1[i] = W1[i];
    __syncthreads();

    int gid = blockIdx.x * blockDim.x + threadIdx.x;
    int node = gid / HID;
    int j    = gid % HID;
    if (node >= n) return;

    const float* xr = x + (size_t)node * F_IN;
    float acc = 0.0f;
    #pragma unroll 16
    for (int k = 0; k < F_IN; k++)
        acc = fmaf(__ldg(xr + k), sW1[k * HID + j], acc);
    g_h1[node * HID + j] = acc;
}

// 3) degree scatter, int4-vectorized (4 edges per thread)
__global__ void k_deg_scatter(const int* __restrict__ dst, int e) {
    int i = blockIdx.x * blockDim.x + threadIdx.x;
    int e4 = e >> 2;
    if (i < e4) {
        int4 d = ((const int4*)dst)[i];
        atomicAdd(&g_deg[d.x], 1.0f);
        atomicAdd(&g_deg[d.y], 1.0f);
        atomicAdd(&g_deg[d.z], 1.0f);
        atomicAdd(&g_deg[d.w], 1.0f);
    } else {
        int base = e4 * 4 + (i - e4);
        if (base < e) atomicAdd(&g_deg[dst[base]], 1.0f);
    }
}

// 4) dinv + self-loop init of agg1, float4-coalesced (4 threads per node)
__global__ void k_dinv_self1(int n) {
    int tid = blockIdx.x * blockDim.x + threadIdx.x;
    int node = tid >> 2;
    int j    = tid & 3;
    if (node >= n) return;
    float di = rsqrtf(g_deg[node]);
    if (j == 0) g_dinv[node] = di;
    float w = di * di;
    float4 h = *(const float4*)(g_h1 + node * HID + j * 4);
    *(float4*)(g_agg1 + node * HID + j * 4) =
        make_float4(w * h.x, w * h.y, w * h.z, w * h.w);
}

// 4b) per-edge weight: w[e] = dinv[src]*dinv[dst] (4 edges per thread)
__global__ void k_edge_w(const int* __restrict__ src,
                         const int* __restrict__ dst, int e) {
    int i = blockIdx.x * blockDim.x + threadIdx.x;
    int e4 = e >> 2;
    if (i < e4) {
        int4 s = ((const int4*)src)[i];
        int4 d = ((const int4*)dst)[i];
        float4 w;
        w.x = g_dinv[s.x] * g_dinv[d.x];
        w.y = g_dinv[s.y] * g_dinv[d.y];
        w.z = g_dinv[s.z] * g_dinv[d.z];
        w.w = g_dinv[s.w] * g_dinv[d.w];
        ((float4*)g_w)[i] = w;
    } else {
        int base = e4 * 4 + (i - e4);
        if (base < e) g_w[base] = g_dinv[src[base]] * g_dinv[dst[base]];
    }
}

// 5) layer-1 edge scatter: 4 threads/edge, 2 edges/thread (MLP), v4 RED
__global__ void k_edge1(const int* __restrict__ src,
                        const int* __restrict__ dst, int e) {
    int h = (e + 1) >> 1;
    long long gid = (long long)blockIdx.x * blockDim.x + threadIdx.x;
    int q = (int)(gid >> 2);
    int j = (int)(gid & 3);
    if (q >= h) return;
    int eA = q, eB = q + h;
    bool hasB = eB < e;

    int sA = src[eA], dA = dst[eA];
    float wA = g_w[eA];
    int sB = 0, dB = 0; float wB = 0.0f;
    if (hasB) { sB = src[eB]; dB = dst[eB]; wB = g_w[eB]; }

    float4 hA = *(const float4*)(g_h1 + sA * HID + j * 4);
    float4 hB = hasB ? *(const float4*)(g_h1 + sB * HID + j * 4)
                     : make_float4(0, 0, 0, 0);

    red_add_v4(g_agg1 + dA * HID + j * 4,
               make_float4(wA * hA.x, wA * hA.y, wA * hA.z, wA * hA.w));
    if (hasB)
        red_add_v4(g_agg1 + dB * HID + j * 4,
                   make_float4(wB * hB.x, wB * hB.y, wB * hB.z, wB * hB.w));
}

// 6) h2 = relu(agg1 + b1) @ W2; fused self-loop init of agg2
__global__ void k_layer2_self2(const float* __restrict__ b1,
                               const float* __restrict__ W2, int n) {
    __shared__ float sW2[HID * NCLS];
    __shared__ float sb1[HID];
    if (threadIdx.x < HID * NCLS) sW2[threadIdx.x] = W2[threadIdx.x];
    if (threadIdx.x < HID) sb1[threadIdx.x] = b1[threadIdx.x];
    __syncthreads();

    int gid = blockIdx.x * blockDim.x + threadIdx.x;
    int node = gid / NCLS;
    int c    = gid % NCLS;
    if (node >= n) return;

    float acc = 0.0f;
    #pragma unroll
    for (int j = 0; j < HID; j++) {
        float v = g_agg1[node * HID + j] + sb1[j];
        v = fmaxf(v, 0.0f);
        acc = fmaf(v, sW2[j * NCLS + c], acc);
    }
    g_h2[node * NCLS + c] = acc;
    float di = g_dinv[node];
    g_agg2[node * NCLS + c] = di * di * acc;
}

// 7) layer-2 edge scatter: 2 threads/edge, 2 edges/thread, v4 RED
__global__ void k_edge2(const int* __restrict__ src,
                        const int* __restrict__ dst, int e) {
    int h = (e + 1) >> 1;
    long long gid = (long long)blockIdx.x * blockDim.x + threadIdx.x;
    int q = (int)(gid >> 1);
    int j = (int)(gid & 1);
    if (q >= h) return;
    int eA = q, eB = q + h;
    bool hasB = eB < e;

    int sA = src[eA], dA = dst[eA];
    float wA = g_w[eA];
    int sB = 0, dB = 0; float wB = 0.0f;
    if (hasB) { sB = src[eB]; dB = dst[eB]; wB = g_w[eB]; }

    float4 hA = *(const float4*)(g_h2 + sA * NCLS + j * 4);
    float4 hB = hasB ? *(const float4*)(g_h2 + sB * NCLS + j * 4)
                     : make_float4(0, 0, 0, 0);

    red_add_v4(g_agg2 + dA * NCLS + j * 4,
               make_float4(wA * hA.x, wA * hA.y, wA * hA.z, wA * hA.w));
    if (hasB)
        red_add_v4(g_agg2 + dB * NCLS + j * 4,
                   make_float4(wB * hB.x, wB * hB.y, wB * hB.z, wB * hB.w));
}

// 8) log_softmax per node (float4 loads)
__global__ void k_logsoftmax(const float* __restrict__ b2,
                             float* __restrict__ out, int n) {
    __shared__ float sb2[NCLS];
    if (threadIdx.x < NCLS) sb2[threadIdx.x] = b2[threadIdx.x];
    __syncthreads();

    int i = blockIdx.x * blockDim.x + threadIdx.x;
    if (i >= n) return;

    float4 a = *(const float4*)(g_agg2 + i * NCLS);
    float4 b = *(const float4*)(g_agg2 + i * NCLS + 4);
    float z[NCLS] = {a.x + sb2[0], a.y + sb2[1], a.z + sb2[2], a.w + sb2[3],
                     b.x + sb2[4], b.y + sb2[5], b.z + sb2[6], b.w + sb2[7]};
    float m = z[0];
    #pragma unroll
    for (int c = 1; c < NCLS; c++) m = fmaxf(m, z[c]);
    float sum = 0.0f;
    #pragma unroll
    for (int c = 0; c < NCLS; c++) sum += expf(z[c] - m);
    float lse = m + logf(sum);
    *(float4*)(out + i * NCLS)     = make_float4(z[0]-lse, z[1]-lse, z[2]-lse, z[3]-lse);
    *(float4*)(out + i * NCLS + 4) = make_float4(z[4]-lse, z[5]-lse, z[6]-lse, z[7]-lse);
}

// ---------------------------------------------------------------------------
extern "C" void kernel_launch(void* const* d_in, const int* in_sizes, int n_in,
                              void* d_out, int out_size) {
    const float* x  = (const float*)d_in[0];
    const int*   ei = (const int*)d_in[1];    // [2, E] int32
    const float* W1 = (const float*)d_in[2];
    const float* b1 = (const float*)d_in[3];
    const float* W2 = (const float*)d_in[4];
    const float* b2 = (const float*)d_in[5];
    float*       out = (float*)d_out;

    const int n = in_sizes[0] / F_IN;      // 100000
    const int e = in_sizes[1] / 2;         // 3200000
    const int* src = ei;
    const int* dst = ei + e;

    const int T = 256;
    int e4t = (e >> 2) + (e & 3);          // threads for 4-wide edge kernels

    k_init_deg<<<(n + T - 1) / T, T>>>(n);
    k_xw1<<<((long long)n * HID + T - 1) / T, T>>>(x, W1, n);
    k_deg_scatter<<<(e4t + T - 1) / T, T>>>(dst, e);
    k_dinv_self1<<<((long long)n * 4 + T - 1) / T, T>>>(n);
    k_edge_w<<<(e4t + T - 1) / T, T>>>(src, dst, e);
    {
        long long total = (long long)((e + 1) >> 1) * 4;
        k_edge1<<<(unsigned)((total + T - 1) / T), T>>>(src, dst, e);
    }
    k_layer2_self2<<<((long long)n * NCLS + T - 1) / T, T>>>(b1, W2, n);
    {
        long long total = (long long)((e + 1) >> 1) * 2;
        k_edge2<<<(unsigned)((total + T - 1) / T), T>>>(src, dst, e);
    }
    k_logsoftmax<<<(n + T - 1) / T, T>>>(b2, out, n);
}

// round 7
// speedup vs baseline: 1.7175x; 1.1621x over previous
#include <cuda_runtime.h>
#include <stdint.h>

#define F_IN 128
#define HID  16
#define NCLS 8
#define MAX_N 100000

__device__ float g_deg [MAX_N];
__device__ float g_dinv[MAX_N];
__device__ float g_h1s [MAX_N * HID];   // dinv[n] * (x@W1)[n]
__device__ float g_agg1[MAX_N * HID];   // pre-scale accumulator: final = dinv*agg1
__device__ float g_h2s [MAX_N * NCLS];  // dinv[n] * h2[n]
__device__ float g_agg2[MAX_N * NCLS];  // pre-scale accumulator

__device__ __forceinline__ void red_add_v4(float* p, float4 v) {
    asm volatile("red.global.add.v4.f32 [%0], {%1, %2, %3, %4};"
                 :: "l"(p), "f"(v.x), "f"(v.y), "f"(v.z), "f"(v.w) : "memory");
}

// 0) deg init: self-loop contributes 1
__global__ void k_init_deg(int n) {
    int i = blockIdx.x * blockDim.x + threadIdx.x;
    if (i < n) g_deg[i] = 1.0f;
}

// 1) degree scatter, int4-vectorized (4 edges per thread)
__global__ void k_deg_scatter(const int* __restrict__ dst, int e) {
    int i = blockIdx.x * blockDim.x + threadIdx.x;
    int e4 = e >> 2;
    if (i < e4) {
        int4 d = ((const int4*)dst)[i];
        atomicAdd(&g_deg[d.x], 1.0f);
        atomicAdd(&g_deg[d.y], 1.0f);
        atomicAdd(&g_deg[d.z], 1.0f);
        atomicAdd(&g_deg[d.w], 1.0f);
    } else {
        int base = e4 * 4 + (i - e4);
        if (base < e) atomicAdd(&g_deg[dst[base]], 1.0f);
    }
}

// 2) FUSED: h1 = x@W1; dinv = rsqrt(deg); h1s = dinv*h1;
//    self-loop init: agg1 = h1s  (consumer multiplies by dinv -> dinv^2 * h1)
__global__ void k_xw1_fused(const float* __restrict__ x,
                            const float* __restrict__ W1, int n) {
    __shared__ float sW1[F_IN * HID];
    for (int i = threadIdx.x; i < F_IN * HID; i += blockDim.x)
        sW1[i] = W1[i];
    __syncthreads();

    int gid = blockIdx.x * blockDim.x + threadIdx.x;
    int node = gid / HID;
    int j    = gid % HID;
    if (node >= n) return;

    const float* xr = x + (size_t)node * F_IN;
    float acc = 0.0f;
    #pragma unroll 16
    for (int k = 0; k < F_IN; k++)
        acc = fmaf(__ldg(xr + k), sW1[k * HID + j], acc);

    float di = rsqrtf(g_deg[node]);     // broadcast within 16-thread group
    if (j == 0) g_dinv[node] = di;
    float hs = di * acc;
    g_h1s [node * HID + j] = hs;
    g_agg1[node * HID + j] = hs;        // self-loop term (pre-scale form)
}

// 3) layer-1 edge scatter: 4 threads/edge, 2 edges/thread — NO weights needed
__global__ void k_edge1(const int* __restrict__ src,
                        const int* __restrict__ dst, int e) {
    int h = (e + 1) >> 1;
    long long gid = (long long)blockIdx.x * blockDim.x + threadIdx.x;
    int q = (int)(gid >> 2);
    int j = (int)(gid & 3);
    if (q >= h) return;
    int eA = q, eB = q + h;
    bool hasB = eB < e;

    int sA = src[eA], dA = dst[eA];
    int sB = 0, dB = 0;
    if (hasB) { sB = src[eB]; dB = dst[eB]; }

    float4 hA = *(const float4*)(g_h1s + sA * HID + j * 4);
    red_add_v4(g_agg1 + dA * HID + j * 4, hA);
    if (hasB) {
        float4 hB = *(const float4*)(g_h1s + sB * HID + j * 4);
        red_add_v4(g_agg1 + dB * HID + j * 4, hB);
    }
}

// 4) h2 = relu(dinv*agg1 + b1) @ W2; h2s = dinv*h2;
//    self-loop init: agg2 = h2s
__global__ void k_layer2(const float* __restrict__ b1,
                         const float* __restrict__ W2, int n) {
    __shared__ float sW2[HID * NCLS];
    __shared__ float sb1[HID];
    if (threadIdx.x < HID * NCLS) sW2[threadIdx.x] = W2[threadIdx.x];
    if (threadIdx.x < HID) sb1[threadIdx.x] = b1[threadIdx.x];
    __syncthreads();

    int gid = blockIdx.x * blockDim.x + threadIdx.x;
    int node = gid / NCLS;
    int c    = gid % NCLS;
    if (node >= n) return;

    float di = g_dinv[node];
    float acc = 0.0f;
    #pragma unroll
    for (int j = 0; j < HID; j++) {
        float v = fmaf(di, g_agg1[node * HID + j], sb1[j]);
        v = fmaxf(v, 0.0f);
        acc = fmaf(v, sW2[j * NCLS + c], acc);
    }
    float hs = di * acc;
    g_h2s [node * NCLS + c] = hs;
    g_agg2[node * NCLS + c] = hs;
}

// 5) layer-2 edge scatter: 2 threads/edge, 2 edges/thread
__global__ void k_edge2(const int* __restrict__ src,
                        const int* __restrict__ dst, int e) {
    int h = (e + 1) >> 1;
    long long gid = (long long)blockIdx.x * blockDim.x + threadIdx.x;
    int q = (int)(gid >> 1);
    int j = (int)(gid & 1);
    if (q >= h) return;
    int eA = q, eB = q + h;
    bool hasB = eB < e;

    int sA = src[eA], dA = dst[eA];
    int sB = 0, dB = 0;
    if (hasB) { sB = src[eB]; dB = dst[eB]; }

    float4 hA = *(const float4*)(g_h2s + sA * NCLS + j * 4);
    red_add_v4(g_agg2 + dA * NCLS + j * 4, hA);
    if (hasB) {
        float4 hB = *(const float4*)(g_h2s + sB * NCLS + j * 4);
        red_add_v4(g_agg2 + dB * NCLS + j * 4, hB);
    }
}

// 6) logits = dinv*agg2 + b2 -> log_softmax
__global__ void k_logsoftmax(const float* __restrict__ b2,
                             float* __restrict__ out, int n) {
    __shared__ float sb2[NCLS];
    if (threadIdx.x < NCLS) sb2[threadIdx.x] = b2[threadIdx.x];
    __syncthreads();

    int i = blockIdx.x * blockDim.x + threadIdx.x;
    if (i >= n) return;

    float di = g_dinv[i];
    float4 a = *(const float4*)(g_agg2 + i * NCLS);
    float4 b = *(const float4*)(g_agg2 + i * NCLS + 4);
    float z[NCLS] = {fmaf(di, a.x, sb2[0]), fmaf(di, a.y, sb2[1]),
                     fmaf(di, a.z, sb2[2]), fmaf(di, a.w, sb2[3]),
                     fmaf(di, b.x, sb2[4]), fmaf(di, b.y, sb2[5]),
                     fmaf(di, b.z, sb2[6]), fmaf(di, b.w, sb2[7])};
    float m = z[0];
    #pragma unroll
    for (int c = 1; c < NCLS; c++) m = fmaxf(m, z[c]);
    float sum = 0.0f;
    #pragma unroll
    for (int c = 0; c < NCLS; c++) sum += expf(z[c] - m);
    float lse = m + logf(sum);
    *(float4*)(out + i * NCLS)     = make_float4(z[0]-lse, z[1]-lse, z[2]-lse, z[3]-lse);
    *(float4*)(out + i * NCLS + 4) = make_float4(z[4]-lse, z[5]-lse, z[6]-lse, z[7]-lse);
}

// ---------------------------------------------------------------------------
extern "C" void kernel_launch(void* const* d_in, const int* in_sizes, int n_in,
                              void* d_out, int out_size) {
    const float* x  = (const float*)d_in[0];
    const int*   ei = (const int*)d_in[1];    // [2, E] int32
    const float* W1 = (const float*)d_in[2];
    const float* b1 = (const float*)d_in[3];
    const float* W2 = (const float*)d_in[4];
    const float* b2 = (const float*)d_in[5];
    float*       out = (float*)d_out;

    const int n = in_sizes[0] / F_IN;      // 100000
    const int e = in_sizes[1] / 2;         // 3200000
    const int* src = ei;
    const int* dst = ei + e;

    const int T = 256;
    int e4t = (e >> 2) + (e & 3);

    k_init_deg<<<(n + T - 1) / T, T>>>(n);                                  // 0
    k_deg_scatter<<<(e4t + T - 1) / T, T>>>(dst, e);                        // 1
    k_xw1_fused<<<((long long)n * HID + T - 1) / T, T>>>(x, W1, n);         // 2
    {
        long long total = (long long)((e + 1) >> 1) * 4;
        k_edge1<<<(unsigned)((total + T - 1) / T), T>>>(src, dst, e);       // 3 (profiled)
    }
    k_layer2<<<((long long)n * NCLS + T - 1) / T, T>>>(b1, W2, n);          // 4
    {
        long long total = (long long)((e + 1) >> 1) * 2;
        k_edge2<<<(unsigned)((total + T - 1) / T), T>>>(src, dst, e);       // 5
    }
    k_logsoftmax<<<(n + T - 1) / T, T>>>(b2, out, n);                       // 6
}